// round 14
// baseline (speedup 1.0000x reference)
#include <cuda_runtime.h>
#include <math.h>
#include <mma.h>

using namespace nvcuda;

// Problem constants
#define NNODES 10000
#define NEDGES 160000
#define DFEAT  512
#define DOUT   256

// ---------------- scratch (no allocations allowed) ----------------
__device__ __align__(16) float g_bufA[NNODES * DFEAT];
__device__ __align__(16) float g_bufB[NNODES * DFEAT];
__device__ __align__(16) float g_bufC[NNODES * DFEAT];
__device__ __align__(16) float g_dinv [NNODES];
__device__ __align__(16) float g_self [NNODES];
__device__ __align__(16) float g_dinvC[NNODES];
__device__ __align__(16) int   g_cnt[NNODES];
__device__ __align__(16) int   g_off[NNODES + 1];
__device__ __align__(16) int   g_ins[NNODES];
__device__ __align__(16) int   g_row[NEDGES];
__device__ __align__(16) int   g_col[NEDGES];
__device__ __align__(16) char  g_ok [NEDGES];
__device__ __align__(16) int   g_rowS [NEDGES];
__device__ __align__(16) float g_normS[NEDGES];
__device__ __align__(16) float g_normCS[NEDGES];
__device__ int g_is64;

template<int S>
__device__ __forceinline__ float* buf() {
    if constexpr (S == 0) return g_bufA;
    else if constexpr (S == 1) return g_bufB;
    else return g_bufC;
}

__device__ __forceinline__ float celuf(float x) {
    return x > 0.0f ? x : expm1f(x);
}

namespace {
struct EagerLoad {
    EagerLoad() {
        void* p = nullptr;
        cudaGetSymbolAddress(&p, g_bufA);
        (void)p;
    }
};
static EagerLoad _eager_load_instance;
}

// ---------------- dtype probe ----------------
__global__ void k_detect(const int* __restrict__ ei32) {
    __shared__ int any;
    if (threadIdx.x == 0) any = 0;
    __syncthreads();
    int v = ei32[2 * threadIdx.x + 1];
    if (v != 0) atomicOr(&any, 1);
    __syncthreads();
    if (threadIdx.x == 0) g_is64 = (any == 0) ? 1 : 0;
}

// ---------------- edge preprocessing ----------------
__global__ void k_init() {
    int i = blockIdx.x * blockDim.x + threadIdx.x;
    if (i < NNODES) { g_dinv[i] = 1.0f; g_dinvC[i] = 0.0f; g_cnt[i] = 0; }
}

__global__ void k_edge1(const int* __restrict__ ei32, const float* __restrict__ w) {
    int e = blockIdx.x * blockDim.x + threadIdx.x;
    if (e >= NEDGES) return;
    int r, c;
    if (g_is64) {
        r = ei32[2 * e];
        c = ei32[2 * (NEDGES + e)];
    } else {
        r = ei32[e];
        c = ei32[NEDGES + e];
    }
    bool ok = ((unsigned)r < NNODES) && ((unsigned)c < NNODES);
    if (!ok) { r = 0; c = 0; }
    g_row[e] = r; g_col[e] = c; g_ok[e] = ok ? 1 : 0;
    if (ok) {
        float we = w[e];
        atomicAdd(&g_dinv[c], we);
        if (r != c) atomicAdd(&g_dinvC[r], we);
    }
    atomicAdd(&g_cnt[c], 1);
}

// hierarchical exclusive scan of g_cnt -> g_off/g_ins
__global__ void k_scan() {
    __shared__ int wsum[32];
    int t = threadIdx.x;
    int lane = t & 31, wi = t >> 5;
    const int CH = (NNODES + 1023) / 1024;
    int lo = t * CH, hi = min(lo + CH, NNODES);
    int s = 0;
    for (int i = lo; i < hi; i++) s += g_cnt[i];
    int v = s;
    #pragma unroll
    for (int d = 1; d < 32; d <<= 1) {
        int n = __shfl_up_sync(0xFFFFFFFFu, v, d);
        if (lane >= d) v += n;
    }
    if (lane == 31) wsum[wi] = v;
    __syncthreads();
    if (wi == 0) {
        int w = wsum[lane];
        #pragma unroll
        for (int d = 1; d < 32; d <<= 1) {
            int n = __shfl_up_sync(0xFFFFFFFFu, w, d);
            if (lane >= d) w += n;
        }
        wsum[lane] = w;
    }
    __syncthreads();
    int excl = (v - s) + (wi > 0 ? wsum[wi - 1] : 0);
    int run = excl;
    for (int i = lo; i < hi; i++) {
        g_off[i] = run; g_ins[i] = run; run += g_cnt[i];
    }
    if (t == 0) g_off[NNODES] = wsum[31];
}

__global__ void k_dinv() {
    int i = blockIdx.x * blockDim.x + threadIdx.x;
    if (i >= NNODES) return;
    float d  = g_dinv[i];
    float di = rsqrtf(d);
    g_dinv[i] = di;
    g_self[i] = di * di;
    float dc = g_dinvC[i];
    g_dinvC[i] = (dc > 0.0f) ? rsqrtf(dc) : 0.0f;
}

__global__ void k_edge2(const float* __restrict__ w) {
    int e = blockIdx.x * blockDim.x + threadIdx.x;
    if (e >= NEDGES) return;
    int r = g_row[e], c = g_col[e];
    float we = g_ok[e] ? w[e] : 0.0f;
    float nv  = g_dinv[r] * we * g_dinv[c];
    float w0  = (r == c) ? 0.0f : we;
    float nvc = g_dinvC[r] * w0 * g_dinvC[c];
    int pos = atomicAdd(&g_ins[c], 1);
    g_rowS[pos]   = r;
    g_normS[pos]  = nv;
    g_normCS[pos] = nvc;
}

// ---------------- SpMM (gather by dest-CSR) ----------------
// MODE 0: GCN : dst = celu(sum_e norm*src[row] + self[c]*src[c] + bias)
// MODE 1: lhat: dst = -sum_e normC*src[row]
// MODE 2: Tx2 : dst = -2*sum_e normC*src[row] - sub[c]
template<int MODE, int SRC, int DST, int SUB>
__global__ void __launch_bounds__(128)
k_spmm(const float* __restrict__ bias) {
    const float* src = buf<SRC>();
    float*       dst = buf<DST>();
    int c = blockIdx.x;
    int t = threadIdx.x;
    int beg = g_off[c], end = g_off[c + 1];
    float4 acc = make_float4(0.f, 0.f, 0.f, 0.f);
    int k = beg;
    for (; k + 1 < end; k += 2) {
        float nv0 = (MODE == 0) ? g_normS[k]     : g_normCS[k];
        float nv1 = (MODE == 0) ? g_normS[k + 1] : g_normCS[k + 1];
        int r0 = g_rowS[k], r1 = g_rowS[k + 1];
        float4 s0 = ((const float4*)(src + r0 * DFEAT))[t];
        float4 s1 = ((const float4*)(src + r1 * DFEAT))[t];
        acc.x += nv0 * s0.x + nv1 * s1.x;
        acc.y += nv0 * s0.y + nv1 * s1.y;
        acc.z += nv0 * s0.z + nv1 * s1.z;
        acc.w += nv0 * s0.w + nv1 * s1.w;
    }
    if (k < end) {
        float nv = (MODE == 0) ? g_normS[k] : g_normCS[k];
        int r = g_rowS[k];
        float4 s = ((const float4*)(src + r * DFEAT))[t];
        acc.x += nv * s.x; acc.y += nv * s.y; acc.z += nv * s.z; acc.w += nv * s.w;
    }
    if (MODE == 0) {
        float sn = g_self[c];
        float4 s = ((const float4*)(src + c * DFEAT))[t];
        float4 b = ((const float4*)bias)[t];
        acc.x = celuf(acc.x + sn * s.x + b.x);
        acc.y = celuf(acc.y + sn * s.y + b.y);
        acc.z = celuf(acc.z + sn * s.z + b.z);
        acc.w = celuf(acc.w + sn * s.w + b.w);
    } else if (MODE == 1) {
        acc.x = -acc.x; acc.y = -acc.y; acc.z = -acc.z; acc.w = -acc.w;
    } else {
        const float* sub = buf<SUB>();
        float4 sb = ((const float4*)(sub + c * DFEAT))[t];
        acc.x = -2.f * acc.x - sb.x;
        acc.y = -2.f * acc.y - sb.y;
        acc.z = -2.f * acc.z - sb.z;
        acc.w = -2.f * acc.w - sb.w;
    }
    ((float4*)(dst + c * DFEAT))[t] = acc;
}

// ---------------- TF32 tensor-core GEMM with register-staged prefetch -------------
// 128x128 tile, BK=32, 256 threads (8 warps 2x4), wmma m16n16k8.
#define ALD 40
#define BLD 136
#define SLD 20   // epilogue staging leading dim: MUST be multiple of 4 for fp32 wmma

// GCN GEMM: C = A @ B (no epilogue; spmm handles bias/celu)
template<int ASEL, int CSEL>
__global__ void __launch_bounds__(256)
k_tgemm(const float* __restrict__ Ain,
        const float* __restrict__ B,
        float* __restrict__ Cout,
        int M, int N, int K) {
    const float* A;
    if constexpr (ASEL >= 0) A = buf<ASEL>(); else A = Ain;
    float* C;
    if constexpr (CSEL >= 0) C = buf<CSEL>(); else C = Cout;

    __shared__ float As[128][ALD];
    __shared__ float Bs[32][BLD];

    int tid = threadIdx.x;
    int wid = tid >> 5;
    int warp_m = wid >> 2;
    int warp_n = wid & 3;
    int mBase = blockIdx.x * 128;
    int nBase = blockIdx.y * 128;

    wmma::fragment<wmma::accumulator, 16, 16, 8, float> cf[4][2];
    #pragma unroll
    for (int mi = 0; mi < 4; mi++)
        #pragma unroll
        for (int ni = 0; ni < 2; ni++)
            wmma::fill_fragment(cf[mi][ni], 0.0f);

    int ar = tid >> 3;
    int ac = (tid & 7) * 4;
    int br = tid >> 5;
    int bc = (tid & 31) * 4;

    float4 av[4], bv[4];
    #pragma unroll
    for (int i = 0; i < 4; i++) {
        int row = mBase + ar + 32 * i;
        av[i] = (row < M) ? *(const float4*)(A + (size_t)row * K + ac)
                          : make_float4(0.f, 0.f, 0.f, 0.f);
        bv[i] = *(const float4*)(B + (size_t)(br + 8 * i) * N + nBase + bc);
    }

    for (int k0 = 0; k0 < K; k0 += 32) {
        #pragma unroll
        for (int i = 0; i < 4; i++) {
            As[ar + 32 * i][ac + 0] = wmma::__float_to_tf32(av[i].x);
            As[ar + 32 * i][ac + 1] = wmma::__float_to_tf32(av[i].y);
            As[ar + 32 * i][ac + 2] = wmma::__float_to_tf32(av[i].z);
            As[ar + 32 * i][ac + 3] = wmma::__float_to_tf32(av[i].w);
            Bs[br + 8 * i][bc + 0] = wmma::__float_to_tf32(bv[i].x);
            Bs[br + 8 * i][bc + 1] = wmma::__float_to_tf32(bv[i].y);
            Bs[br + 8 * i][bc + 2] = wmma::__float_to_tf32(bv[i].z);
            Bs[br + 8 * i][bc + 3] = wmma::__float_to_tf32(bv[i].w);
        }
        __syncthreads();
        int kn = k0 + 32;
        if (kn < K) {
            #pragma unroll
            for (int i = 0; i < 4; i++) {
                int row = mBase + ar + 32 * i;
                av[i] = (row < M) ? *(const float4*)(A + (size_t)row * K + kn + ac)
                                  : make_float4(0.f, 0.f, 0.f, 0.f);
                bv[i] = *(const float4*)(B + (size_t)(kn + br + 8 * i) * N + nBase + bc);
            }
        }
        #pragma unroll
        for (int ks = 0; ks < 4; ks++) {
            wmma::fragment<wmma::matrix_a, 16, 16, 8, wmma::precision::tf32, wmma::row_major> af[4];
            wmma::fragment<wmma::matrix_b, 16, 16, 8, wmma::precision::tf32, wmma::row_major> bf[2];
            #pragma unroll
            for (int mi = 0; mi < 4; mi++)
                wmma::load_matrix_sync(af[mi], &As[warp_m * 64 + mi * 16][ks * 8], ALD);
            #pragma unroll
            for (int ni = 0; ni < 2; ni++)
                wmma::load_matrix_sync(bf[ni], &Bs[ks * 8][warp_n * 32 + ni * 16], BLD);
            #pragma unroll
            for (int mi = 0; mi < 4; mi++)
                #pragma unroll
                for (int ni = 0; ni < 2; ni++)
                    wmma::mma_sync(cf[mi][ni], af[mi], bf[ni], cf[mi][ni]);
        }
        __syncthreads();
    }

    #pragma unroll
    for (int mi = 0; mi < 4; mi++) {
        int row = mBase + warp_m * 64 + mi * 16;
        if (row >= M) continue;
        #pragma unroll
        for (int ni = 0; ni < 2; ni++) {
            int col = nBase + warp_n * 32 + ni * 16;
            wmma::store_matrix_sync(C + (size_t)row * N + col, cf[mi][ni], N, wmma::mem_row_major);
        }
    }
}

// Fused Cheb GEMM: out = celu([Tx0|Tx1|Tx2] @ Wc_flat + bc)
// A segments: k in [0,512)=bufB(Tx0), [512,1024)=bufA(Tx1), [1024,1536)=bufC(Tx2).
// B = Wc viewed as [1536, 256] (contiguous). M=NNODES, N=DOUT.
__global__ void __launch_bounds__(256)
k_cgemm(const float* __restrict__ B,
        const float* __restrict__ bias,
        float* __restrict__ C) {
    const int M = NNODES, N = DOUT, K = 3 * DFEAT;

    __shared__ float As[128][ALD];
    __shared__ float Bs[32][BLD];
    __shared__ __align__(128) float stage[8][16][SLD];

    int tid = threadIdx.x;
    int lane = tid & 31;
    int wid = tid >> 5;
    int warp_m = wid >> 2;
    int warp_n = wid & 3;
    int mBase = blockIdx.x * 128;
    int nBase = blockIdx.y * 128;

    wmma::fragment<wmma::accumulator, 16, 16, 8, float> cf[4][2];
    #pragma unroll
    for (int mi = 0; mi < 4; mi++)
        #pragma unroll
        for (int ni = 0; ni < 2; ni++)
            wmma::fill_fragment(cf[mi][ni], 0.0f);

    int ar = tid >> 3;
    int ac = (tid & 7) * 4;
    int br = tid >> 5;
    int bc = (tid & 31) * 4;

    float4 av[4], bv[4];
    {
        const float* A = g_bufB;  // segment 0 (Tx0)
        #pragma unroll
        for (int i = 0; i < 4; i++) {
            int row = mBase + ar + 32 * i;
            av[i] = (row < M) ? *(const float4*)(A + (size_t)row * DFEAT + ac)
                              : make_float4(0.f, 0.f, 0.f, 0.f);
            bv[i] = *(const float4*)(B + (size_t)(br + 8 * i) * N + nBase + bc);
        }
    }

    for (int k0 = 0; k0 < K; k0 += 32) {
        #pragma unroll
        for (int i = 0; i < 4; i++) {
            As[ar + 32 * i][ac + 0] = wmma::__float_to_tf32(av[i].x);
            As[ar + 32 * i][ac + 1] = wmma::__float_to_tf32(av[i].y);
            As[ar + 32 * i][ac + 2] = wmma::__float_to_tf32(av[i].z);
            As[ar + 32 * i][ac + 3] = wmma::__float_to_tf32(av[i].w);
            Bs[br + 8 * i][bc + 0] = wmma::__float_to_tf32(bv[i].x);
            Bs[br + 8 * i][bc + 1] = wmma::__float_to_tf32(bv[i].y);
            Bs[br + 8 * i][bc + 2] = wmma::__float_to_tf32(bv[i].z);
            Bs[br + 8 * i][bc + 3] = wmma::__float_to_tf32(bv[i].w);
        }
        __syncthreads();
        int kn = k0 + 32;
        if (kn < K) {
            const float* A = (kn < 512) ? g_bufB : (kn < 1024) ? g_bufA : g_bufC;
            int koff = kn & 511;
            #pragma unroll
            for (int i = 0; i < 4; i++) {
                int row = mBase + ar + 32 * i;
                av[i] = (row < M) ? *(const float4*)(A + (size_t)row * DFEAT + koff + ac)
                                  : make_float4(0.f, 0.f, 0.f, 0.f);
                bv[i] = *(const float4*)(B + (size_t)(kn + br + 8 * i) * N + nBase + bc);
            }
        }
        #pragma unroll
        for (int ks = 0; ks < 4; ks++) {
            wmma::fragment<wmma::matrix_a, 16, 16, 8, wmma::precision::tf32, wmma::row_major> af[4];
            wmma::fragment<wmma::matrix_b, 16, 16, 8, wmma::precision::tf32, wmma::row_major> bf[2];
            #pragma unroll
            for (int mi = 0; mi < 4; mi++)
                wmma::load_matrix_sync(af[mi], &As[warp_m * 64 + mi * 16][ks * 8], ALD);
            #pragma unroll
            for (int ni = 0; ni < 2; ni++)
                wmma::load_matrix_sync(bf[ni], &Bs[ks * 8][warp_n * 32 + ni * 16], BLD);
            #pragma unroll
            for (int mi = 0; mi < 4; mi++)
                #pragma unroll
                for (int ni = 0; ni < 2; ni++)
                    wmma::mma_sync(cf[mi][ni], af[mi], bf[ni], cf[mi][ni]);
        }
        __syncthreads();
    }

    // epilogue: bias + celu via per-warp smem staging (ldm=SLD=20, multiple of 4)
    int sr = lane >> 1;             // 0..15
    int sc = (lane & 1) * 8;        // 0 or 8
    #pragma unroll
    for (int mi = 0; mi < 4; mi++) {
        int rowBase = mBase + warp_m * 64 + mi * 16;
        #pragma unroll
        for (int ni = 0; ni < 2; ni++) {
            int colBase = nBase + warp_n * 32 + ni * 16;
            wmma::store_matrix_sync(&stage[wid][0][0], cf[mi][ni], SLD, wmma::mem_row_major);
            __syncwarp();
            int row = rowBase + sr;
            if (row < M) {
                float* cp = C + (size_t)row * N + colBase + sc;
                #pragma unroll
                for (int j = 0; j < 8; j++) {
                    float v = stage[wid][sr][sc + j] + bias[colBase + sc + j];
                    cp[j] = celuf(v);
                }
            }
            __syncwarp();
        }
    }
}

// ---------------- launch ----------------
extern "C" void kernel_launch(void* const* d_in, const int* in_sizes, int n_in,
                              void* d_out, int out_size) {
    const float* x  = (const float*)d_in[0];
    const int*   ei = (const int*)d_in[1];
    const float* w  = (const float*)d_in[2];
    const float* W1 = (const float*)d_in[3];
    const float* b1 = (const float*)d_in[4];
    const float* W2 = (const float*)d_in[5];
    const float* b2 = (const float*)d_in[6];
    const float* Wc = (const float*)d_in[7];
    const float* bc = (const float*)d_in[8];
    float* out = (float*)d_out;

    k_detect<<<1, 512>>>(ei);
    k_init  <<<(NNODES + 255) / 256, 256>>>();
    k_edge1 <<<(NEDGES + 255) / 256, 256>>>(ei, w);
    k_scan  <<<1, 1024>>>();
    k_dinv  <<<(NNODES + 255) / 256, 256>>>();
    k_edge2 <<<(NEDGES + 255) / 256, 256>>>(w);

    dim3 blk(256);
    dim3 g512((NNODES + 127) / 128, 4);
    dim3 g256((NNODES + 127) / 128, 2);

    // GCN layer 1: bufA = x @ W1 ; bufB = celu(spmm(bufA) + self + b1)
    k_tgemm<-1, 0><<<g512, blk>>>(x, W1, nullptr, NNODES, 512, 512);
    k_spmm<0, 0, 1, 0><<<NNODES, 128>>>(b1);

    // GCN layer 2
    k_tgemm<1, 0><<<g512, blk>>>(nullptr, W2, nullptr, NNODES, 512, 512);
    k_spmm<0, 0, 1, 0><<<NNODES, 128>>>(b2);

    // Cheb: Tx0 = bufB; Tx1 = bufA; Tx2 = bufC; fused GEMM with bias+celu epilogue
    k_spmm<1, 1, 0, 0><<<NNODES, 128>>>(nullptr);   // bufA = Tx1 = lhat(Tx0)
    k_spmm<2, 0, 2, 1><<<NNODES, 128>>>(nullptr);   // bufC = Tx2 = 2*lhat(Tx1) - Tx0
    k_cgemm<<<g256, blk>>>(Wc, bc, out);
}

// round 15
// speedup vs baseline: 1.1832x; 1.1832x over previous
#include <cuda_runtime.h>
#include <cuda_pipeline.h>
#include <math.h>
#include <mma.h>

using namespace nvcuda;

// Problem constants
#define NNODES 10000
#define NEDGES 160000
#define DFEAT  512
#define DOUT   256

// ---------------- scratch (no allocations allowed) ----------------
__device__ __align__(16) float g_bufA[NNODES * DFEAT];
__device__ __align__(16) float g_bufB[NNODES * DFEAT];
__device__ __align__(16) float g_bufC[NNODES * DFEAT];
__device__ __align__(16) float g_w12[2 * DFEAT * DFEAT];   // tf32(W1), tf32(W2)
__device__ __align__(16) float g_wc [3 * DFEAT * DOUT];    // tf32(Wc) as [1536,256]
__device__ __align__(16) float g_dinv [NNODES];
__device__ __align__(16) float g_self [NNODES];
__device__ __align__(16) float g_dinvC[NNODES];
__device__ __align__(16) int   g_cnt[NNODES];
__device__ __align__(16) int   g_off[NNODES + 1];
__device__ __align__(16) int   g_ins[NNODES];
__device__ __align__(16) int   g_row[NEDGES];
__device__ __align__(16) int   g_col[NEDGES];
__device__ __align__(16) char  g_ok [NEDGES];
__device__ __align__(16) int   g_rowS [NEDGES];
__device__ __align__(16) float g_normS[NEDGES];
__device__ __align__(16) float g_normCS[NEDGES];
__device__ int g_is64;

template<int S>
__device__ __forceinline__ float* buf() {
    if constexpr (S == 0) return g_bufA;
    else if constexpr (S == 1) return g_bufB;
    else return g_bufC;
}

__device__ __forceinline__ float celuf(float x) {
    return x > 0.0f ? x : expm1f(x);
}

namespace {
struct EagerLoad {
    EagerLoad() {
        void* p = nullptr;
        cudaGetSymbolAddress(&p, g_bufA);
        (void)p;
    }
};
static EagerLoad _eager_load_instance;
}

// ---------------- dtype probe ----------------
__global__ void k_detect(const int* __restrict__ ei32) {
    __shared__ int any;
    if (threadIdx.x == 0) any = 0;
    __syncthreads();
    int v = ei32[2 * threadIdx.x + 1];
    if (v != 0) atomicOr(&any, 1);
    __syncthreads();
    if (threadIdx.x == 0) g_is64 = (any == 0) ? 1 : 0;
}

// ---------------- tf32 pre-conversion (round-to-nearest) ----------------
// D: 0 -> g_bufC, 1 -> g_w12, 2 -> g_wc.  n4/dstOff4 are float4 counts.
template<int D>
__global__ void k_cvt(const float* __restrict__ src, int n4, int dstOff4) {
    float* dst = (D == 0) ? g_bufC : (D == 1) ? g_w12 : g_wc;
    int i = blockIdx.x * blockDim.x + threadIdx.x;
    if (i < n4) {
        float4 v = ((const float4*)src)[i];
        float4 o;
        o.x = wmma::__float_to_tf32(v.x);
        o.y = wmma::__float_to_tf32(v.y);
        o.z = wmma::__float_to_tf32(v.z);
        o.w = wmma::__float_to_tf32(v.w);
        ((float4*)dst)[dstOff4 + i] = o;
    }
}

// ---------------- edge preprocessing ----------------
__global__ void k_init() {
    int i = blockIdx.x * blockDim.x + threadIdx.x;
    if (i < NNODES) { g_dinv[i] = 1.0f; g_dinvC[i] = 0.0f; g_cnt[i] = 0; }
}

__global__ void k_edge1(const int* __restrict__ ei32, const float* __restrict__ w) {
    int e = blockIdx.x * blockDim.x + threadIdx.x;
    if (e >= NEDGES) return;
    int r, c;
    if (g_is64) {
        r = ei32[2 * e];
        c = ei32[2 * (NEDGES + e)];
    } else {
        r = ei32[e];
        c = ei32[NEDGES + e];
    }
    bool ok = ((unsigned)r < NNODES) && ((unsigned)c < NNODES);
    if (!ok) { r = 0; c = 0; }
    g_row[e] = r; g_col[e] = c; g_ok[e] = ok ? 1 : 0;
    if (ok) {
        float we = w[e];
        atomicAdd(&g_dinv[c], we);
        if (r != c) atomicAdd(&g_dinvC[r], we);
    }
    atomicAdd(&g_cnt[c], 1);
}

// hierarchical exclusive scan of g_cnt -> g_off/g_ins
__global__ void k_scan() {
    __shared__ int wsum[32];
    int t = threadIdx.x;
    int lane = t & 31, wi = t >> 5;
    const int CH = (NNODES + 1023) / 1024;
    int lo = t * CH, hi = min(lo + CH, NNODES);
    int s = 0;
    for (int i = lo; i < hi; i++) s += g_cnt[i];
    int v = s;
    #pragma unroll
    for (int d = 1; d < 32; d <<= 1) {
        int n = __shfl_up_sync(0xFFFFFFFFu, v, d);
        if (lane >= d) v += n;
    }
    if (lane == 31) wsum[wi] = v;
    __syncthreads();
    if (wi == 0) {
        int w = wsum[lane];
        #pragma unroll
        for (int d = 1; d < 32; d <<= 1) {
            int n = __shfl_up_sync(0xFFFFFFFFu, w, d);
            if (lane >= d) w += n;
        }
        wsum[lane] = w;
    }
    __syncthreads();
    int excl = (v - s) + (wi > 0 ? wsum[wi - 1] : 0);
    int run = excl;
    for (int i = lo; i < hi; i++) {
        g_off[i] = run; g_ins[i] = run; run += g_cnt[i];
    }
    if (t == 0) g_off[NNODES] = wsum[31];
}

__global__ void k_dinv() {
    int i = blockIdx.x * blockDim.x + threadIdx.x;
    if (i >= NNODES) return;
    float d  = g_dinv[i];
    float di = rsqrtf(d);
    g_dinv[i] = di;
    g_self[i] = di * di;
    float dc = g_dinvC[i];
    g_dinvC[i] = (dc > 0.0f) ? rsqrtf(dc) : 0.0f;
}

__global__ void k_edge2(const float* __restrict__ w) {
    int e = blockIdx.x * blockDim.x + threadIdx.x;
    if (e >= NEDGES) return;
    int r = g_row[e], c = g_col[e];
    float we = g_ok[e] ? w[e] : 0.0f;
    float nv  = g_dinv[r] * we * g_dinv[c];
    float w0  = (r == c) ? 0.0f : we;
    float nvc = g_dinvC[r] * w0 * g_dinvC[c];
    int pos = atomicAdd(&g_ins[c], 1);
    g_rowS[pos]   = r;
    g_normS[pos]  = nv;
    g_normCS[pos] = nvc;
}

// ---------------- SpMM (gather by dest-CSR) ----------------
// MODE 0: GCN : dst = tf32(celu(sum norm*src[row] + self*src[c] + bias))
// MODE 1: lhat: dst = tf32(-sum normC*src[row])
// MODE 2: Tx2 : dst = tf32(-2*sum normC*src[row] - sub[c])
// Outputs are rounded to tf32: they feed tensor-core GEMMs via raw cp.async.
template<int MODE, int SRC, int DST, int SUB>
__global__ void __launch_bounds__(128)
k_spmm(const float* __restrict__ bias) {
    const float* src = buf<SRC>();
    float*       dst = buf<DST>();
    int c = blockIdx.x;
    int t = threadIdx.x;
    int beg = g_off[c], end = g_off[c + 1];
    float4 acc = make_float4(0.f, 0.f, 0.f, 0.f);
    int k = beg;
    for (; k + 3 < end; k += 4) {
        float nv0 = (MODE == 0) ? g_normS[k]     : g_normCS[k];
        float nv1 = (MODE == 0) ? g_normS[k + 1] : g_normCS[k + 1];
        float nv2 = (MODE == 0) ? g_normS[k + 2] : g_normCS[k + 2];
        float nv3 = (MODE == 0) ? g_normS[k + 3] : g_normCS[k + 3];
        int r0 = g_rowS[k], r1 = g_rowS[k + 1], r2 = g_rowS[k + 2], r3 = g_rowS[k + 3];
        float4 s0 = ((const float4*)(src + r0 * DFEAT))[t];
        float4 s1 = ((const float4*)(src + r1 * DFEAT))[t];
        float4 s2 = ((const float4*)(src + r2 * DFEAT))[t];
        float4 s3 = ((const float4*)(src + r3 * DFEAT))[t];
        acc.x += nv0 * s0.x + nv1 * s1.x + nv2 * s2.x + nv3 * s3.x;
        acc.y += nv0 * s0.y + nv1 * s1.y + nv2 * s2.y + nv3 * s3.y;
        acc.z += nv0 * s0.z + nv1 * s1.z + nv2 * s2.z + nv3 * s3.z;
        acc.w += nv0 * s0.w + nv1 * s1.w + nv2 * s2.w + nv3 * s3.w;
    }
    for (; k < end; k++) {
        float nv = (MODE == 0) ? g_normS[k] : g_normCS[k];
        int r = g_rowS[k];
        float4 s = ((const float4*)(src + r * DFEAT))[t];
        acc.x += nv * s.x; acc.y += nv * s.y; acc.z += nv * s.z; acc.w += nv * s.w;
    }
    if (MODE == 0) {
        float sn = g_self[c];
        float4 s = ((const float4*)(src + c * DFEAT))[t];
        float4 b = ((const float4*)bias)[t];
        acc.x = wmma::__float_to_tf32(celuf(acc.x + sn * s.x + b.x));
        acc.y = wmma::__float_to_tf32(celuf(acc.y + sn * s.y + b.y));
        acc.z = wmma::__float_to_tf32(celuf(acc.z + sn * s.z + b.z));
        acc.w = wmma::__float_to_tf32(celuf(acc.w + sn * s.w + b.w));
    } else if (MODE == 1) {
        acc.x = wmma::__float_to_tf32(-acc.x);
        acc.y = wmma::__float_to_tf32(-acc.y);
        acc.z = wmma::__float_to_tf32(-acc.z);
        acc.w = wmma::__float_to_tf32(-acc.w);
    } else {
        const float* sub = buf<SUB>();
        float4 sb = ((const float4*)(sub + c * DFEAT))[t];
        acc.x = wmma::__float_to_tf32(-2.f * acc.x - sb.x);
        acc.y = wmma::__float_to_tf32(-2.f * acc.y - sb.y);
        acc.z = wmma::__float_to_tf32(-2.f * acc.z - sb.z);
        acc.w = wmma::__float_to_tf32(-2.f * acc.w - sb.w);
    }
    ((float4*)(dst + c * DFEAT))[t] = acc;
}

// ---------------- TF32 tensor-core GEMM, cp.async double-buffered -------------
// 128x128 tile, BK=16, 256 threads (8 warps as 2x4), wmma m16n16k8.
// Inputs pre-rounded to tf32; cp.async copies raw 16B chunks.
#define ALD 20     // As leading dim (floats), mult of 4
#define BLD 132    // Bs leading dim, mult of 4
#define SLD 20     // epilogue staging ldm, mult of 4

// GCN GEMM: g_bufA = buf<ASEL> @ tf32W(g_w12+BOFF).  M=NNODES, N=K=512.
template<int ASEL, int BOFF>
__global__ void __launch_bounds__(256, 2)
k_tgemm() {
    constexpr int M = NNODES, N = DFEAT, K = DFEAT;
    constexpr int NT = K / 16;

    const float* A  = buf<ASEL>();
    const float* Bw = g_w12 + BOFF;
    float*       C  = g_bufA;

    __shared__ float As[2][128][ALD];
    __shared__ float Bs[2][16][BLD];

    int tid = threadIdx.x;
    int wid = tid >> 5;
    int warp_m = wid >> 2;
    int warp_n = wid & 3;
    int mBase = blockIdx.x * 128;
    int nBase = blockIdx.y * 128;

    wmma::fragment<wmma::accumulator, 16, 16, 8, float> cf[4][2];
    #pragma unroll
    for (int mi = 0; mi < 4; mi++)
        #pragma unroll
        for (int ni = 0; ni < 2; ni++)
            wmma::fill_fragment(cf[mi][ni], 0.0f);

    int ar = tid >> 2;            // 0..63  (handles rows ar, ar+64)
    int ac = (tid & 3) * 4;       // 0..12
    int br = tid >> 5;            // 0..7   (handles rows br, br+8)
    int bc = (tid & 31) * 4;      // 0..124

    auto issue = [&](int kt, int bsel) {
        int k0 = kt * 16;
        #pragma unroll
        for (int i = 0; i < 2; i++) {
            int r = ar + 64 * i;
            int grow = mBase + r;
            if (grow < M)
                __pipeline_memcpy_async(&As[bsel][r][ac],
                                        A + (size_t)grow * K + k0 + ac, 16);
            else
                *(float4*)&As[bsel][r][ac] = make_float4(0.f, 0.f, 0.f, 0.f);
            __pipeline_memcpy_async(&Bs[bsel][br + 8 * i][bc],
                                    Bw + (size_t)(k0 + br + 8 * i) * N + nBase + bc, 16);
        }
    };

    issue(0, 0);
    __pipeline_commit();

    for (int kt = 0; kt < NT; kt++) {
        int cur = kt & 1;
        if (kt + 1 < NT) {
            issue(kt + 1, cur ^ 1);
            __pipeline_commit();
            __pipeline_wait_prior(1);
        } else {
            __pipeline_wait_prior(0);
        }
        __syncthreads();
        #pragma unroll
        for (int ks = 0; ks < 2; ks++) {
            wmma::fragment<wmma::matrix_a, 16, 16, 8, wmma::precision::tf32, wmma::row_major> af[4];
            wmma::fragment<wmma::matrix_b, 16, 16, 8, wmma::precision::tf32, wmma::row_major> bf[2];
            #pragma unroll
            for (int mi = 0; mi < 4; mi++)
                wmma::load_matrix_sync(af[mi], &As[cur][warp_m * 64 + mi * 16][ks * 8], ALD);
            #pragma unroll
            for (int ni = 0; ni < 2; ni++)
                wmma::load_matrix_sync(bf[ni], &Bs[cur][ks * 8][warp_n * 32 + ni * 16], BLD);
            #pragma unroll
            for (int mi = 0; mi < 4; mi++)
                #pragma unroll
                for (int ni = 0; ni < 2; ni++)
                    wmma::mma_sync(cf[mi][ni], af[mi], bf[ni], cf[mi][ni]);
        }
        __syncthreads();
    }

    #pragma unroll
    for (int mi = 0; mi < 4; mi++) {
        int row = mBase + warp_m * 64 + mi * 16;
        if (row >= M) continue;
        #pragma unroll
        for (int ni = 0; ni < 2; ni++) {
            int col = nBase + warp_n * 32 + ni * 16;
            wmma::store_matrix_sync(C + (size_t)row * N + col, cf[mi][ni], N, wmma::mem_row_major);
        }
    }
}

// Fused Cheb GEMM: out = celu([Tx0|Tx1|Tx2] @ tf32(Wc) + bc)
// A segments: tiles 0-31 = bufB(Tx0), 32-63 = bufA(Tx1), 64-95 = bufC(Tx2).
__global__ void __launch_bounds__(256, 2)
k_cgemm(const float* __restrict__ bias, float* __restrict__ C) {
    constexpr int M = NNODES, N = DOUT, K = 3 * DFEAT;
    constexpr int NT = K / 16;   // 96

    const float* Bw = g_wc;

    __shared__ float As[2][128][ALD];
    __shared__ float Bs[2][16][BLD];
    __shared__ __align__(128) float stage[8][16][SLD];

    int tid = threadIdx.x;
    int lane = tid & 31;
    int wid = tid >> 5;
    int warp_m = wid >> 2;
    int warp_n = wid & 3;
    int mBase = blockIdx.x * 128;
    int nBase = blockIdx.y * 128;

    wmma::fragment<wmma::accumulator, 16, 16, 8, float> cf[4][2];
    #pragma unroll
    for (int mi = 0; mi < 4; mi++)
        #pragma unroll
        for (int ni = 0; ni < 2; ni++)
            wmma::fill_fragment(cf[mi][ni], 0.0f);

    int ar = tid >> 2;
    int ac = (tid & 3) * 4;
    int br = tid >> 5;
    int bc = (tid & 31) * 4;

    auto issue = [&](int kt, int bsel) {
        const float* A = (kt < 32) ? g_bufB : (kt < 64) ? g_bufA : g_bufC;
        int k0 = (kt & 31) * 16;
        #pragma unroll
        for (int i = 0; i < 2; i++) {
            int r = ar + 64 * i;
            int grow = mBase + r;
            if (grow < M)
                __pipeline_memcpy_async(&As[bsel][r][ac],
                                        A + (size_t)grow * DFEAT + k0 + ac, 16);
            else
                *(float4*)&As[bsel][r][ac] = make_float4(0.f, 0.f, 0.f, 0.f);
            __pipeline_memcpy_async(&Bs[bsel][br + 8 * i][bc],
                                    Bw + (size_t)(kt * 16 + br + 8 * i) * N + nBase + bc, 16);
        }
    };

    issue(0, 0);
    __pipeline_commit();

    for (int kt = 0; kt < NT; kt++) {
        int cur = kt & 1;
        if (kt + 1 < NT) {
            issue(kt + 1, cur ^ 1);
            __pipeline_commit();
            __pipeline_wait_prior(1);
        } else {
            __pipeline_wait_prior(0);
        }
        __syncthreads();
        #pragma unroll
        for (int ks = 0; ks < 2; ks++) {
            wmma::fragment<wmma::matrix_a, 16, 16, 8, wmma::precision::tf32, wmma::row_major> af[4];
            wmma::fragment<wmma::matrix_b, 16, 16, 8, wmma::precision::tf32, wmma::row_major> bf[2];
            #pragma unroll
            for (int mi = 0; mi < 4; mi++)
                wmma::load_matrix_sync(af[mi], &As[cur][warp_m * 64 + mi * 16][ks * 8], ALD);
            #pragma unroll
            for (int ni = 0; ni < 2; ni++)
                wmma::load_matrix_sync(bf[ni], &Bs[cur][ks * 8][warp_n * 32 + ni * 16], BLD);
            #pragma unroll
            for (int mi = 0; mi < 4; mi++)
                #pragma unroll
                for (int ni = 0; ni < 2; ni++)
                    wmma::mma_sync(cf[mi][ni], af[mi], bf[ni], cf[mi][ni]);
        }
        __syncthreads();
    }

    // epilogue: bias + celu via per-warp smem staging (ldm=SLD=20, mult of 4)
    int sr = lane >> 1;
    int sc = (lane & 1) * 8;
    #pragma unroll
    for (int mi = 0; mi < 4; mi++) {
        int rowBase = mBase + warp_m * 64 + mi * 16;
        #pragma unroll
        for (int ni = 0; ni < 2; ni++) {
            int colBase = nBase + warp_n * 32 + ni * 16;
            wmma::store_matrix_sync(&stage[wid][0][0], cf[mi][ni], SLD, wmma::mem_row_major);
            __syncwarp();
            int row = rowBase + sr;
            if (row < M) {
                float* cp = C + (size_t)row * N + colBase + sc;
                #pragma unroll
                for (int j = 0; j < 8; j++) {
                    float v = stage[wid][sr][sc + j] + bias[colBase + sc + j];
                    cp[j] = celuf(v);
                }
            }
            __syncwarp();
        }
    }
}

// ---------------- launch ----------------
extern "C" void kernel_launch(void* const* d_in, const int* in_sizes, int n_in,
                              void* d_out, int out_size) {
    const float* x  = (const float*)d_in[0];
    const int*   ei = (const int*)d_in[1];
    const float* w  = (const float*)d_in[2];
    const float* W1 = (const float*)d_in[3];
    const float* b1 = (const float*)d_in[4];
    const float* W2 = (const float*)d_in[5];
    const float* b2 = (const float*)d_in[6];
    const float* Wc = (const float*)d_in[7];
    const float* bc = (const float*)d_in[8];
    float* out = (float*)d_out;

    // edge preprocessing + dest-CSR build
    k_detect<<<1, 512>>>(ei);
    k_init  <<<(NNODES + 255) / 256, 256>>>();
    k_edge1 <<<(NEDGES + 255) / 256, 256>>>(ei, w);
    k_scan  <<<1, 1024>>>();
    k_dinv  <<<(NNODES + 255) / 256, 256>>>();
    k_edge2 <<<(NEDGES + 255) / 256, 256>>>(w);

    // tf32 pre-conversions
    const int XN4 = NNODES * DFEAT / 4;
    const int WN4 = DFEAT * DFEAT / 4;
    const int CN4 = 3 * DFEAT * DOUT / 4;
    k_cvt<0><<<(XN4 + 255) / 256, 256>>>(x,  XN4, 0);     // bufC = tf32(x)
    k_cvt<1><<<(WN4 + 255) / 256, 256>>>(W1, WN4, 0);
    k_cvt<1><<<(WN4 + 255) / 256, 256>>>(W2, WN4, WN4);
    k_cvt<2><<<(CN4 + 255) / 256, 256>>>(Wc, CN4, 0);

    dim3 blk(256);
    dim3 g512((NNODES + 127) / 128, 4);
    dim3 g256((NNODES + 127) / 128, 2);

    // GCN layer 1: bufA = tf32(x)@W1 ; bufB = tf32(celu(spmm(bufA)+self+b1))
    k_tgemm<2, 0><<<g512, blk>>>();
    k_spmm<0, 0, 1, 0><<<NNODES, 128>>>(b1);

    // GCN layer 2: bufA = bufB@W2 ; bufB = ...
    k_tgemm<1, DFEAT * DFEAT><<<g512, blk>>>();
    k_spmm<0, 0, 1, 0><<<NNODES, 128>>>(b2);

    // Cheb: Tx0 = bufB; Tx1 = bufA; Tx2 = bufC; fused GEMM w/ bias+celu epilogue
    k_spmm<1, 1, 0, 0><<<NNODES, 128>>>(nullptr);   // bufA = Tx1 = lhat(Tx0)
    k_spmm<2, 0, 2, 1><<<NNODES, 128>>>(nullptr);   // bufC = Tx2 = 2*lhat(Tx1) - Tx0
    k_cgemm<<<g256, blk>>>(bc, out);
}